// round 6
// baseline (speedup 1.0000x reference)
#include <cuda_runtime.h>
#include <cuda_bf16.h>

// ---------------------------------------------------------------------------
// VoxelDistill: heatmap (centerpoint-style gaussian max) + fused
// conv1x1 -> trilinear-downsample -> masked L1 distill loss.
//
// Algebra: all three lin_resize stages have weight exactly 0.5, so
// resize(conv(x)) == conv(avg8(x)). We average the 8 student taps per
// channel first (d in {4D+1,4D+2}, h in {2H,2H+1}, w in {2W,2W+1}),
// then one 128x64 matvec per output position.
// ---------------------------------------------------------------------------

#define EPS32F 1.1920928955078125e-7f
#define MAX_BOXES 256

__device__ float g_hm[2 * 128 * 128];   // [D][H][W]  == hm[gx=H][gy=W][gz=D]
__device__ float g_sum;

__device__ __forceinline__ float gauss_radius(float h, float w) {
    const float ov = 0.1f;
    float b1 = h + w;
    float c1 = w * h * (1.0f - ov) / (1.0f + ov);
    float r1 = (b1 + sqrtf(fmaxf(b1 * b1 - 4.0f * c1, 0.0f))) / 2.0f;
    float b2 = 2.0f * (h + w);
    float c2 = (1.0f - ov) * w * h;
    float r2 = (b2 + sqrtf(fmaxf(b2 * b2 - 16.0f * c2, 0.0f))) / 2.0f;
    float b3 = -2.0f * ov * (h + w);
    float c3 = (ov - 1.0f) * w * h;
    float r3 = (b3 + sqrtf(fmaxf(b3 * b3 - 16.0f * ov * c3, 0.0f))) / 2.0f;
    return fminf(fminf(r1, r2), r3);
}

__global__ void vd_init_kernel() { g_sum = 0.0f; }

// 32 blocks x 1024 threads = 32768 threads, one per heatmap cell.
__global__ void vd_heatmap_kernel(const float* __restrict__ boxes, int N) {
    __shared__ int   s_cxi[MAX_BOXES], s_cyi[MAX_BOXES], s_czi[MAX_BOXES];
    __shared__ int   s_rx[MAX_BOXES], s_rz[MAX_BOXES], s_valid[MAX_BOXES];
    __shared__ float s_dnx[MAX_BOXES], s_dnz[MAX_BOXES];
    __shared__ float s_part[32];

    int t = threadIdx.x;
    for (int i = t; i < N; i += blockDim.x) {
        float bx = boxes[i * 9 + 0];
        float by = boxes[i * 9 + 1];
        float bz = boxes[i * 9 + 2];
        float wf = boxes[i * 9 + 3] / 0.1f / 8.0f;
        float lf = boxes[i * 9 + 4] / 0.1f / 8.0f;
        float hf = boxes[i * 9 + 5] / 0.2f / 8.0f;

        float r_xy = gauss_radius(lf, wf);
        float r_z  = fmaxf(gauss_radius(lf, hf), gauss_radius(wf, hf));
        int rx = max(2, (int)(r_xy / 0.4f));   // trunc toward zero, matches jnp
        int rz = max(2, (int)(r_z  / 1.0f));

        float cx = (bx + 51.2f) / 0.4f;
        float cy = (by + 51.2f) / 0.4f;
        float cz = (bz + 5.0f)  / 1.0f;
        int cxi = (int)cx;
        int cyi = (int)cy;
        int czi = (int)cz;

        int valid = (wf > 0.0f) && (lf > 0.0f) &&
                    (cxi >= 0) && (cxi < 128) &&
                    (cyi >= 0) && (cyi < 128) &&
                    (czi >= 0) && (czi <= 1);

        float sx = (2.0f * (float)rx + 1.0f) / 6.0f;
        float sz = (2.0f * (float)rz + 1.0f) / 6.0f;

        s_cxi[i] = cxi; s_cyi[i] = cyi; s_czi[i] = czi;
        s_rx[i] = rx;   s_rz[i] = rz;   s_valid[i] = valid;
        s_dnx[i] = 2.0f * sx * sx;      // sy == sx since ry == rx
        s_dnz[i] = 2.0f * sz * sz;
    }
    __syncthreads();

    int cell = blockIdx.x * blockDim.x + t;           // 0..32767
    int D = cell >> 14;
    int rem = cell & 16383;
    int H = rem >> 7;                                  // gx
    int W = rem & 127;                                 // gy

    float m = 0.0f;
    for (int i = 0; i < N; i++) {
        if (!s_valid[i]) continue;
        int dx = H - s_cxi[i];
        int dy = W - s_cyi[i];
        int dz = D - s_czi[i];
        if (abs(dx) <= s_rx[i] && abs(dy) <= s_rx[i] && abs(dz) <= s_rz[i]) {
            float e = (float)(dx * dx) / s_dnx[i]
                    + (float)(dy * dy) / s_dnx[i]
                    + (float)(dz * dz) / s_dnz[i];
            float g = expf(-e);
            if (g >= EPS32F) m = fmaxf(m, g);
        }
    }
    g_hm[cell] = m;

    // block sum -> atomic add into g_sum
    float v = m;
    #pragma unroll
    for (int o = 16; o; o >>= 1) v += __shfl_down_sync(0xffffffffu, v, o);
    if ((t & 31) == 0) s_part[t >> 5] = v;
    __syncthreads();
    if (t < 32) {
        float s = (t < (int)(blockDim.x >> 5)) ? s_part[t] : 0.0f;
        #pragma unroll
        for (int o = 16; o; o >>= 1) s += __shfl_down_sync(0xffffffffu, s, o);
        if (t == 0) atomicAdd(&g_sum, s);
    }
}

// grid (4, 128, 2): block covers 32 output W at fixed (H, D). 256 threads.
__global__ void __launch_bounds__(256)
vd_main_kernel(const float* __restrict__ student,
               const float* __restrict__ teacher,
               const float* __restrict__ conv_w,
               const float* __restrict__ conv_b,
               float* __restrict__ out) {
    __shared__ float sh_w[128 * 64];        // conv_w [o][c], 32 KB
    __shared__ float sh_avg[64][32];        // avg8 student feats [c][wi], 8 KB

    int t  = threadIdx.x;
    int W0 = blockIdx.x * 32;
    int H  = blockIdx.y;
    int D  = blockIdx.z;

    for (int i = t; i < 8192; i += 256) sh_w[i] = conv_w[i];

    // Phase 1: 8-tap average of student into shared.
    // student layout: c:524288, d:65536, h:256, w:1
    int d0 = 4 * D + 1;
    int h0 = 2 * H;
    const float2* sp2 = (const float2*)student;
    for (int e = t; e < 2048; e += 256) {
        int c  = e >> 5;
        int wi = e & 31;
        int base  = c * 524288 + d0 * 65536 + h0 * 256 + 2 * (W0 + wi);
        int b2    = base >> 1;
        float2 a0 = sp2[b2];
        float2 a1 = sp2[b2 + 128];            // h+1
        float2 a2 = sp2[b2 + 32768];          // d+1
        float2 a3 = sp2[b2 + 32768 + 128];    // d+1, h+1
        sh_avg[c][wi] =
            (a0.x + a0.y + a1.x + a1.y + a2.x + a2.y + a3.x + a3.y) * 0.125f;
    }

    // Prefetch epilogue operands while phase-1 stores drain / before compute:
    // teacher values, bias, heatmap factor — all independent of sh_avg.
    int wi = t & 31;
    int og = t >> 5;   // warp id -> uniform per warp (broadcast weight reads)
    int sp = D * 16384 + H * 128 + W0 + wi;   // spatial index (D,H,W)

    float tv[16], bv[16];
    #pragma unroll
    for (int k = 0; k < 16; k++) {
        tv[k] = teacher[(og * 16 + k) * 32768 + sp];
        bv[k] = conv_b[og * 16 + k];
    }
    float f = g_hm[sp] * (10.0f / (g_sum + 1e-4f));

    __syncthreads();

    // Phase 2: each thread = one wi, 16 output channels (o = og*16 + k).
    float acc[16];
    #pragma unroll
    for (int k = 0; k < 16; k++) acc[k] = 0.0f;

    #pragma unroll
    for (int c4 = 0; c4 < 64; c4 += 4) {
        float v0 = sh_avg[c4 + 0][wi];
        float v1 = sh_avg[c4 + 1][wi];
        float v2 = sh_avg[c4 + 2][wi];
        float v3 = sh_avg[c4 + 3][wi];
        #pragma unroll
        for (int k = 0; k < 16; k++) {
            const float4 w4 = *(const float4*)&sh_w[(og * 16 + k) * 64 + c4];
            acc[k] += w4.x * v0 + w4.y * v1 + w4.z * v2 + w4.w * v3;
        }
    }

    #pragma unroll
    for (int k = 0; k < 16; k++) {
        int idx = (og * 16 + k) * 32768 + sp;
        out[idx] = fabsf(acc[k] + bv[k] - tv[k]) * f;
    }
}

extern "C" void kernel_launch(void* const* d_in, const int* in_sizes, int n_in,
                              void* d_out, int out_size) {
    const float* boxes   = (const float*)d_in[0];
    // d_in[1] = gt_labels_3d (unused by reference)
    const float* teacher = (const float*)d_in[2];
    const float* student = (const float*)d_in[3];
    const float* conv_w  = (const float*)d_in[4];
    const float* conv_b  = (const float*)d_in[5];
    int N = in_sizes[0] / 9;
    if (N > MAX_BOXES) N = MAX_BOXES;   // shared staging capacity guard

    vd_init_kernel<<<1, 1>>>();
    vd_heatmap_kernel<<<32, 1024>>>(boxes, N);
    dim3 grid(4, 128, 2);
    vd_main_kernel<<<grid, 256>>>(student, teacher, conv_w, conv_b,
                                  (float*)d_out);
}

// round 7
// speedup vs baseline: 1.8198x; 1.8198x over previous
#include <cuda_runtime.h>
#include <cuda_bf16.h>

// ---------------------------------------------------------------------------
// VoxelDistill: heatmap (centerpoint-style gaussian max) + fused
// conv1x1 -> trilinear-downsample -> masked L1 distill loss.
//
// Algebra: all three lin_resize stages have weight exactly 0.5, so
// resize(conv(x)) == conv(avg8(x)). Average the 8 student taps per channel
// (d in {4D+1,4D+2}, h in {2H,2H+1}, w in {2W,2W+1}), then one 128x64
// matvec per output position.
//
// 2 launches: heatmap (writes g_hm + per-block partial sums) and fused main
// (reduces partials, conv+loss). No init kernel, no atomics.
// ---------------------------------------------------------------------------

#define EPS32F 1.1920928955078125e-7f
#define MAX_BOXES 256

__device__ float g_hm[2 * 128 * 128];   // [D][H][W]  == hm[gx=H][gy=W][gz=D]
__device__ float g_part[128];           // per-heatmap-block partial sums

__device__ __forceinline__ float gauss_radius(float h, float w) {
    const float ov = 0.1f;
    float b1 = h + w;
    float c1 = w * h * (1.0f - ov) / (1.0f + ov);
    float r1 = (b1 + sqrtf(fmaxf(b1 * b1 - 4.0f * c1, 0.0f))) / 2.0f;
    float b2 = 2.0f * (h + w);
    float c2 = (1.0f - ov) * w * h;
    float r2 = (b2 + sqrtf(fmaxf(b2 * b2 - 16.0f * c2, 0.0f))) / 2.0f;
    float b3 = -2.0f * ov * (h + w);
    float c3 = (ov - 1.0f) * w * h;
    float r3 = (b3 + sqrtf(fmaxf(b3 * b3 - 16.0f * ov * c3, 0.0f))) / 2.0f;
    return fminf(fminf(r1, r2), r3);
}

// 128 blocks x 256 threads = 32768 threads, one per heatmap cell.
// Box preprocessing replicated per block (cheap, avoids an extra kernel).
__global__ void __launch_bounds__(256)
vd_heatmap_kernel(const float* __restrict__ boxes, int N) {
    __shared__ int   s_cxi[MAX_BOXES], s_cyi[MAX_BOXES], s_czi[MAX_BOXES];
    __shared__ int   s_rx[MAX_BOXES], s_rz[MAX_BOXES], s_valid[MAX_BOXES];
    __shared__ float s_dnx[MAX_BOXES], s_dnz[MAX_BOXES];
    __shared__ float s_red[8];

    int t = threadIdx.x;
    for (int i = t; i < N; i += 256) {
        float bx = boxes[i * 9 + 0];
        float by = boxes[i * 9 + 1];
        float bz = boxes[i * 9 + 2];
        float wf = boxes[i * 9 + 3] / 0.1f / 8.0f;
        float lf = boxes[i * 9 + 4] / 0.1f / 8.0f;
        float hf = boxes[i * 9 + 5] / 0.2f / 8.0f;

        float r_xy = gauss_radius(lf, wf);
        float r_z  = fmaxf(gauss_radius(lf, hf), gauss_radius(wf, hf));
        int rx = max(2, (int)(r_xy / 0.4f));   // trunc toward zero, matches jnp
        int rz = max(2, (int)(r_z  / 1.0f));

        float cx = (bx + 51.2f) / 0.4f;
        float cy = (by + 51.2f) / 0.4f;
        float cz = (bz + 5.0f)  / 1.0f;
        int cxi = (int)cx;
        int cyi = (int)cy;
        int czi = (int)cz;

        int valid = (wf > 0.0f) && (lf > 0.0f) &&
                    (cxi >= 0) && (cxi < 128) &&
                    (cyi >= 0) && (cyi < 128) &&
                    (czi >= 0) && (czi <= 1);

        float sx = (2.0f * (float)rx + 1.0f) / 6.0f;
        float sz = (2.0f * (float)rz + 1.0f) / 6.0f;

        s_cxi[i] = cxi; s_cyi[i] = cyi; s_czi[i] = czi;
        s_rx[i] = rx;   s_rz[i] = rz;   s_valid[i] = valid;
        s_dnx[i] = 2.0f * sx * sx;      // sy == sx since ry == rx
        s_dnz[i] = 2.0f * sz * sz;
    }
    __syncthreads();

    int cell = blockIdx.x * 256 + t;                   // 0..32767
    int D = cell >> 14;
    int rem = cell & 16383;
    int H = rem >> 7;                                  // gx
    int W = rem & 127;                                 // gy

    float m = 0.0f;
    for (int i = 0; i < N; i++) {
        if (!s_valid[i]) continue;
        int dx = H - s_cxi[i];
        int dy = W - s_cyi[i];
        int dz = D - s_czi[i];
        if (abs(dx) <= s_rx[i] && abs(dy) <= s_rx[i] && abs(dz) <= s_rz[i]) {
            float e = (float)(dx * dx) / s_dnx[i]
                    + (float)(dy * dy) / s_dnx[i]
                    + (float)(dz * dz) / s_dnz[i];
            float g = expf(-e);
            if (g >= EPS32F) m = fmaxf(m, g);
        }
    }
    g_hm[cell] = m;

    // block sum -> g_part[blockIdx] (no atomics, no init kernel)
    float v = m;
    #pragma unroll
    for (int o = 16; o; o >>= 1) v += __shfl_down_sync(0xffffffffu, v, o);
    if ((t & 31) == 0) s_red[t >> 5] = v;
    __syncthreads();
    if (t < 32) {
        float s = (t < 8) ? s_red[t] : 0.0f;
        #pragma unroll
        for (int o = 4; o; o >>= 1) s += __shfl_down_sync(0xffffffffu, s, o);
        if (t == 0) g_part[blockIdx.x] = s;
    }
}

// grid (2, 128, 2): block covers 64 output W at fixed (H, D). 256 threads.
// Each thread: 16 output channels x 2 adjacent W positions.
__global__ void __launch_bounds__(256, 3)
vd_main_kernel(const float* __restrict__ student,
               const float* __restrict__ teacher,
               const float* __restrict__ conv_w,
               const float* __restrict__ conv_b,
               float* __restrict__ out) {
    __shared__ float sh_w[128 * 64];        // conv_w [o][c], 32 KB
    __shared__ float sh_avg[64][64];        // avg8 student feats [c][wi], 16 KB
    __shared__ float sh_b[128];

    int t  = threadIdx.x;
    int W0 = blockIdx.x * 64;
    int H  = blockIdx.y;
    int D  = blockIdx.z;

    // stage conv_w (float4) + conv_b
    {
        const float4* w4p = (const float4*)conv_w;
        float4*       s4p = (float4*)sh_w;
        #pragma unroll
        for (int i = t; i < 2048; i += 256) s4p[i] = w4p[i];
        if (t < 128) sh_b[t] = conv_b[t];
    }

    // heatmap-sum reduce: every warp independently sums the 128 partials.
    float psum;
    {
        int l = t & 31;
        psum = g_part[l] + g_part[l + 32] + g_part[l + 64] + g_part[l + 96];
        #pragma unroll
        for (int o = 16; o; o >>= 1)
            psum += __shfl_xor_sync(0xffffffffu, psum, o);
    }

    // Phase 1: 8-tap average of student into shared (float4 loads).
    // student layout: c:524288, d:65536, h:256, w:1
    // task e: c = e>>5, pair p = e&31 -> outputs wi = 2p, 2p+1
    {
        int d0 = 4 * D + 1;
        int h0 = 2 * H;
        const float4* sp4 = (const float4*)student;
        #pragma unroll
        for (int i = 0; i < 8; i++) {
            int e = t + i * 256;
            int c = e >> 5;
            int p = e & 31;
            int fbase = c * 524288 + d0 * 65536 + h0 * 256 + 2 * W0 + 4 * p;
            int b4 = fbase >> 2;
            float4 q0 = sp4[b4];                    // d0, h0
            float4 q1 = sp4[b4 + 64];               // d0, h0+1
            float4 q2 = sp4[b4 + 16384];            // d0+1, h0
            float4 q3 = sp4[b4 + 16384 + 64];       // d0+1, h0+1
            float o0 = (q0.x + q0.y + q1.x + q1.y +
                        q2.x + q2.y + q3.x + q3.y) * 0.125f;
            float o1 = (q0.z + q0.w + q1.z + q1.w +
                        q2.z + q2.w + q3.z + q3.w) * 0.125f;
            *(float2*)&sh_avg[c][2 * p] = make_float2(o0, o1);
        }
    }
    __syncthreads();

    // Phase 2: lane l handles wi = 2l, 2l+1; warp og handles 16 channels.
    int l  = t & 31;
    int og = t >> 5;
    float acc0[16], acc1[16];
    #pragma unroll
    for (int k = 0; k < 16; k++) { acc0[k] = 0.0f; acc1[k] = 0.0f; }

    #pragma unroll
    for (int c4 = 0; c4 < 64; c4 += 4) {
        float2 va = *(const float2*)&sh_avg[c4 + 0][2 * l];
        float2 vb = *(const float2*)&sh_avg[c4 + 1][2 * l];
        float2 vc = *(const float2*)&sh_avg[c4 + 2][2 * l];
        float2 vd = *(const float2*)&sh_avg[c4 + 3][2 * l];
        #pragma unroll
        for (int k = 0; k < 16; k++) {
            const float4 w4 = *(const float4*)&sh_w[(og * 16 + k) * 64 + c4];
            acc0[k] += w4.x * va.x + w4.y * vb.x + w4.z * vc.x + w4.w * vd.x;
            acc1[k] += w4.x * va.y + w4.y * vb.y + w4.z * vc.y + w4.w * vd.y;
        }
    }

    // Epilogue: loss = |conv + b - teacher| * hm * 10 / (sum + 1e-4)
    float scale = 10.0f / (psum + 1e-4f);
    int sp0 = D * 16384 + H * 128 + W0 + 2 * l;   // spatial index (D,H,W)
    float2 hm2 = *(const float2*)&g_hm[sp0];
    float f0 = hm2.x * scale;
    float f1 = hm2.y * scale;

    #pragma unroll
    for (int k = 0; k < 16; k++) {
        int o   = og * 16 + k;
        int idx = o * 32768 + sp0;
        float2 t2 = *(const float2*)&teacher[idx];
        float  bk = sh_b[o];
        float2 r;
        r.x = fabsf(acc0[k] + bk - t2.x) * f0;
        r.y = fabsf(acc1[k] + bk - t2.y) * f1;
        *(float2*)&out[idx] = r;
    }
}

extern "C" void kernel_launch(void* const* d_in, const int* in_sizes, int n_in,
                              void* d_out, int out_size) {
    const float* boxes   = (const float*)d_in[0];
    // d_in[1] = gt_labels_3d (unused by reference)
    const float* teacher = (const float*)d_in[2];
    const float* student = (const float*)d_in[3];
    const float* conv_w  = (const float*)d_in[4];
    const float* conv_b  = (const float*)d_in[5];
    int N = in_sizes[0] / 9;
    if (N > MAX_BOXES) N = MAX_BOXES;   // shared staging capacity guard

    vd_heatmap_kernel<<<128, 256>>>(boxes, N);
    dim3 grid(2, 128, 2);
    vd_main_kernel<<<grid, 256>>>(student, teacher, conv_w, conv_b,
                                  (float*)d_out);
}